// round 12
// baseline (speedup 1.0000x reference)
#include <cuda_runtime.h>
#include <math.h>
#include <stdint.h>

// RVQE: 12-qubit real statevector recurrent cell, B=64, T=9 (8 scan steps).
// One CTA per batch element; state = 4096 floats = 512 threads x 4 packed f32x2.
// Float index g12 = (t << 3) | r, t: 9 bits, r: 3 bits.
//   r bits: bit0=lane11(anc1), bit1=lane10(anc0), bit2=lane9(PACKED)
//   lane l (0..8) <-> t bit (8-l):
//     t bits 8,7,6,5 (warp-id bits): lanes 0,1,2,3 -> smem exchange
//     t bits 4..0   (warp lane):     lanes 4,5,6,7,8 -> __shfl_xor
// PACKING: P[i], i=(anc0<<1)|anc1; P[i].lo = lane9=0, P[i].hi = lane9=1.
//
// Fused neuron algebra (validated rounds 3/5/8): per stage
//   chain = E(a_0) C_0 G_0 T'(D1) C_1 G_1 ... T'(D9) C_9 G_9 F(a_9)
// Sync scheme: 6 smem exchanges/stage (2 RY 4-way gathers + 4 CiY), ping-pong
// buffers A,B,A,B,A,B with ONE __syncthreads per exchange (reuse-at-distance-2
// is ordered by the intervening exchange's sync; step boundary adds a full
// sync at probs).

namespace {

typedef unsigned long long u64;

constexpr int NTH   = 512;
constexpr int TT    = 9;
constexpr int NSTEP = 8;
constexpr int NIDX  = 22;   // 18 deltas + 2 entries + 2 trailings
constexpr int STq   = 5;    // exch stride in u64 (4 + 1 pad; conflict-free)
constexpr u64 SGN2  = 0x8000000080000000ULL;

__device__ __forceinline__ u64 pk(float lo, float hi) {
    u64 r; asm("mov.b64 %0,{%1,%2};" : "=l"(r) : "f"(lo), "f"(hi)); return r;
}
__device__ __forceinline__ void upk(u64 u, float& lo, float& hi) {
    asm("mov.b64 {%0,%1},%2;" : "=f"(lo), "=f"(hi) : "l"(u));
}
__device__ __forceinline__ u64 bc(float x) { return pk(x, x); }
__device__ __forceinline__ u64 f2mul(u64 a, u64 b) {
    u64 d; asm("mul.rn.f32x2 %0,%1,%2;" : "=l"(d) : "l"(a), "l"(b)); return d;
}
__device__ __forceinline__ u64 f2fma(u64 a, u64 b, u64 c) {
    u64 d; asm("fma.rn.f32x2 %0,%1,%2,%3;" : "=l"(d) : "l"(a), "l"(b), "l"(c)); return d;
}
__device__ __forceinline__ u64 f2neg(u64 a) { return a ^ SGN2; }
__device__ __forceinline__ u64 f2swap(u64 a) { float lo, hi; upk(a, lo, hi); return pk(hi, lo); }

// ---- stage RY pieces ----

// RY on lane9 (packed dim): u' = C*u + (-s,+s)*swap(u)
__device__ __forceinline__ void ry_lane9(u64* P, u64 C, u64 SW) {
#pragma unroll
    for (int i = 0; i < 4; i++)
        P[i] = f2fma(SW, f2swap(P[i]), f2mul(C, P[i]));
}

__device__ __forceinline__ void ry_shfl(u64* P, int t, int m, float c, float s) {
    u64 C = bc(c), SE = bc((t & m) ? s : -s);
#pragma unroll
    for (int i = 0; i < 4; i++) {
        u64 w = __shfl_xor_sync(0xffffffffu, P[i], m);
        P[i] = f2fma(SE, w, f2mul(C, P[i]));
    }
}

// Combined RY on t bits ma, mb: one sync, 4-way gather.
__device__ __forceinline__ void ry_smem4(u64* P, int t, int ma, int mb,
                                         float c0, float s0, float c1, float s1,
                                         u64* X) {
#pragma unroll
    for (int i = 0; i < 4; i++) X[t * STq + i] = P[i];
    __syncthreads();
    int a  = (t & ma) ? 1 : 0;
    int bb = (t & mb) ? 1 : 0;
    float r0a0 = a  ? s0 : c0;
    float r0a1 = a  ? c0 : -s0;
    float r1b0 = bb ? s1 : c1;
    float r1b1 = bb ? c1 : -s1;
    u64 k00 = bc(r0a0 * r1b0), k01 = bc(r0a0 * r1b1);
    u64 k10 = bc(r0a1 * r1b0), k11 = bc(r0a1 * r1b1);
    int base = t & ~(ma | mb);
    const u64* x00 = X + base * STq;
    const u64* x01 = X + (base | mb) * STq;
    const u64* x10 = X + (base | ma) * STq;
    const u64* x11 = X + (base | ma | mb) * STq;
#pragma unroll
    for (int i = 0; i < 4; i++)
        P[i] = f2fma(k00, x00[i],
               f2fma(k01, x01[i],
               f2fma(k10, x10[i], f2mul(k11, x11[i]))));
    // no trailing sync: ping-pong ordering
}

// ---- CiY pieces (ctrl anc1: odd i = {1,3}) ----

__device__ __forceinline__ void ciy_lane9(u64* P) {
#pragma unroll
    for (int i = 1; i < 4; i += 2) {
        float lo, hi; upk(P[i], lo, hi);
        P[i] = pk(hi, -lo);
    }
}

__device__ __forceinline__ void ciy_shfl(u64* P, int t, int m) {
    u64 sgn = (t & m) ? SGN2 : 0ULL;
#pragma unroll
    for (int i = 1; i < 4; i += 2) {
        u64 w = __shfl_xor_sync(0xffffffffu, P[i], m);
        P[i] = w ^ sgn;
    }
}

// Cross-warp CiY: one sync, ping-pong buffer.
__device__ __forceinline__ void ciy_smem(u64* P, int t, int m, u64* X) {
    X[t * STq + 0] = P[1];
    X[t * STq + 1] = P[3];
    __syncthreads();
    const u64* p = X + (t ^ m) * STq;
    u64 sgn = (t & m) ? SGN2 : 0ULL;
    P[1] = p[0] ^ sgn;
    P[3] = p[1] ^ sgn;
    // no trailing sync: ping-pong ordering
}

// ---- fused neuron ops (single group; packed over lane9) ----
// x_i = P[i]: x0=(0,0) x1=(0,1) x2=(1,0) x3=(1,1) of (anc0,anc1)

__device__ __forceinline__ void applyT(u64* P, float cb, float sb, u64 DC, u64 DS) {
    u64 CB = bc(cb), SB = bc(sb), NSB = bc(-sb);
    u64 C  = f2fma(NSB, DS, f2mul(CB, DC));
    u64 S  = f2fma(SB,  DC, f2mul(CB, DS));
    u64 NS = f2neg(S);
    u64 x0 = P[0], x1 = P[1], x2 = P[2], x3 = P[3];
    P[0] = f2fma(S,  x3, f2mul(C, x0));
    P[1] = f2fma(NS, x2, f2mul(C, x1));
    P[2] = f2fma(S,  x1, f2mul(C, x2));
    P[3] = f2fma(NS, x0, f2mul(C, x3));
}

__device__ __forceinline__ void applyE(u64* P, float cb, float sb, u64 DC, u64 DS) {
    u64 CB = bc(cb), SB = bc(sb), NSB = bc(-sb);
    u64 C  = f2fma(NSB, DS, f2mul(CB, DC));
    u64 S  = f2fma(SB,  DC, f2mul(CB, DS));
    u64 NS = f2neg(S);
    u64 x0 = P[0], x1 = P[1], x2 = P[2], x3 = P[3];
    P[0] = f2fma(NS, x2, f2mul(C, x0));
    P[1] = f2fma(NS, x3, f2mul(C, x1));
    P[2] = f2fma(S,  x1, f2mul(C, x3));
    P[3] = f2neg(f2fma(S, x0, f2mul(C, x2)));
}

__device__ __forceinline__ void applyF(u64* P, float cb, float sb, u64 DC, u64 DS) {
    u64 CB = bc(cb), SB = bc(sb), NSB = bc(-sb);
    u64 C  = f2fma(NSB, DS, f2mul(CB, DC));
    u64 S  = f2fma(SB,  DC, f2mul(CB, DS));
    u64 NS = f2neg(S);
    u64 x0 = P[0], x1 = P[1], x2 = P[2], x3 = P[3];
    P[0] = f2fma(NS, x3, f2mul(C, x0));
    P[1] = f2fma(S,  x2, f2mul(C, x1));
    P[2] = f2neg(f2fma(S, x0, f2mul(C, x3)));
    P[3] = f2fma(NS, x1, f2mul(C, x2));
}

// G: rotate (x1, x3) by packed signed angle SE.
__device__ __forceinline__ void applyG(u64* P, u64 C, u64 SE) {
    u64 x1 = P[1], x3 = P[3];
    P[1] = f2fma(f2neg(SE), x3, f2mul(C, x1));
    P[3] = f2fma(SE,        x1, f2mul(C, x3));
}

// angle-vector spec tables
__device__ constexpr int aIdx[NIDX] = {1,2,3,4,5,6,7,8,9, 11,12,13,14,15,16,17,18,19, 0, 10, 9, 19};
__device__ constexpr int bIdx[NIDX] = {0,1,2,3,4,5,6,7,8, 10,11,12,13,14,15,16,17,18, -1,-1,-1,-1};

__global__ void __launch_bounds__(NTH, 1) rvqe_kernel(
    const int*   __restrict__ inputs,   // (64, 9, 6) int32
    const float* __restrict__ ua,       // (2, 10)
    const float* __restrict__ nth,      // (2, 10, 11)
    float*       __restrict__ out,
    int out_size)
{
    __shared__ u64   bufA[NTH * STq];   // 20480 B
    __shared__ u64   bufB[NTH * STq];   // 20480 B
    __shared__ float uc[20], us[20];
    __shared__ u64   DC2[NIDX], DS2[NIDX];  // packed lane9 delta trig
    __shared__ float gc_sm[20], gs_sm[20];
    __shared__ u64   se9p[2];
    __shared__ float probs_sm[64];
    __shared__ int   tIdx[TT];

    const int t = threadIdx.x;
    const int b = blockIdx.x;
    const int* inb = inputs + b * TT * 6;

    // ---- precompute ----
    if (t < 20) {
        float c, s; sincosf(0.5f * ua[t], &s, &c);
        uc[t] = c; us[t] = s;
        float cg, sg; sincosf(0.5f * nth[t * 11 + (t % 10)], &sg, &cg);
        gc_sm[t] = cg; gs_sm[t] = sg;
        if ((t % 10) == 9) se9p[t / 10] = pk(-sg, sg);
    }
    if (t < NIDX) {
        const float* A = nth + aIdx[t] * 11;
        const float* Bp = (bIdx[t] >= 0) ? (nth + bIdx[t] * 11) : nullptr;
        float d9 = A[9] - (Bp ? Bp[9] : 0.f);
        float ch, sh; sincosf(0.5f * d9, &sh, &ch);
        DC2[t] = pk(1.f, ch);
        DS2[t] = pk(0.f, sh);
    }
    if (t < TT) {
        int idx = 0;
#pragma unroll
        for (int i = 0; i < 6; i++) idx |= (inb[t * 6 + i] & 1) << (5 - i);
        tIdx[t] = idx;
    }

    // per-thread base trig in REGISTERS (lane i -> t bit (8-i), i=0..8)
    float cbs[NIDX], sbs[NIDX];
#pragma unroll
    for (int idx = 0; idx < NIDX; idx++) {
        const float* A = nth + aIdx[idx] * 11;
        const float* Bp = (bIdx[idx] >= 0) ? (nth + bIdx[idx] * 11) : nullptr;
        float base = A[10] - (Bp ? Bp[10] : 0.f);
#pragma unroll
        for (int i = 0; i < 9; i++)
            if ((t >> (8 - i)) & 1) base += A[i] - (Bp ? Bp[i] : 0.f);
        float c, s; sincosf(0.5f * base, &s, &c);
        cbs[idx] = c; sbs[idx] = s;
    }
    __syncthreads();

    // ---- init state: g12 = tIdx[0]<<6 -> thread tIdx[0]<<3, r=0 (lo of P[0]) ----
    u64 P[4];
#pragma unroll
    for (int i = 0; i < 4; i++) P[i] = 0ULL;
    if (t == (tIdx[0] << 3)) P[0] = pk(1.f, 0.f);

    for (int step = 0; step < NSTEP; step++) {
#pragma unroll
        for (int s = 0; s < 2; s++) {
            const float* ucc = uc + s * 10;
            const float* uss = us + s * 10;

            // stage RYs: lane9 packed; lanes 4..8 shfl; lanes 0,1 and 2,3 smem
            {
                u64 C9 = bc(ucc[9]);
                u64 SW = pk(-uss[9], uss[9]);
                ry_lane9(P, C9, SW);
            }
#pragma unroll
            for (int l = 4; l <= 8; l++)
                ry_shfl(P, t, 1 << (8 - l), ucc[l], uss[l]);
            ry_smem4(P, t, 256, 128, ucc[0], uss[0], ucc[1], uss[1], bufA);
            ry_smem4(P, t,  64,  32, ucc[2], uss[2], ucc[3], uss[3], bufB);

            // neuron chain: E C0 G0 T' C1 G1 ... T' C9 G9 F
            applyE(P, cbs[18 + s], sbs[18 + s], DC2[18 + s], DS2[18 + s]);
            ciy_smem(P, t, 256, bufA);                 // C0 (lane0 = t bit8)
            applyG(P, bc(gc_sm[s * 10]),
                   bc(((t >> 8) & 1) ? gs_sm[s * 10] : -gs_sm[s * 10]));
#pragma unroll
            for (int n = 1; n < 10; n++) {
                int di = s * 9 + n - 1;
                applyT(P, cbs[di], sbs[di], DC2[di], DS2[di]);
                if (n == 9) {
                    ciy_lane9(P);
                } else if (n >= 4) {
                    ciy_shfl(P, t, 1 << (8 - n));      // lanes 4..8
                } else if (n == 1) {
                    ciy_smem(P, t, 128, bufB);
                } else if (n == 2) {
                    ciy_smem(P, t, 64, bufA);
                } else {
                    ciy_smem(P, t, 32, bufB);
                }
                int gi = s * 10 + n;
                u64 C = bc(gc_sm[gi]);
                if (n <= 8) {
                    applyG(P, C, bc(((t >> (8 - n)) & 1) ? gs_sm[gi] : -gs_sm[gi]));
                } else {
                    applyG(P, C, se9p[s]);
                }
            }
            applyF(P, cbs[20 + s], sbs[20 + s], DC2[20 + s], DS2[20 + s]);
        }

        // ---- probs: out index j = t >> 3 (lanes 0..5 = t bits 8..3);
        //      reduce over t bits 0..2 (lanes 6,7,8) + packed halves ----
        u64 acc = 0ULL;
#pragma unroll
        for (int i = 0; i < 4; i++) acc = f2fma(P[i], P[i], acc);
        float alo, ahi; upk(acc, alo, ahi);
        float ssq = alo + ahi;
        ssq += __shfl_xor_sync(0xffffffffu, ssq, 1);
        ssq += __shfl_xor_sync(0xffffffffu, ssq, 2);
        ssq += __shfl_xor_sync(0xffffffffu, ssq, 4);
        if (!(t & 7)) {
            probs_sm[t >> 3] = ssq;
            out[(b * NSTEP + step) * 64 + (t >> 3)] = ssq;
        }
        __syncthreads();

        // ---- project + normalize; cond_flips cancel across steps ----
        int tj = tIdx[step + 1];
        float invn = 1.0f / sqrtf(probs_sm[tj]);
        if ((t >> 3) == tj) {
            u64 INV = bc(invn);
#pragma unroll
            for (int i = 0; i < 4; i++) P[i] = f2mul(INV, P[i]);
        } else {
#pragma unroll
            for (int i = 0; i < 4; i++) P[i] = 0ULL;
        }
    }

    // ---- second tuple output: measured = inputs[:,1:] as float ----
    if (out_size > 32768 && t < 48) {
        out[32768 + b * 48 + t] = (float)inb[6 + t];
    }
}

} // namespace

extern "C" void kernel_launch(void* const* d_in, const int* in_sizes, int n_in,
                              void* d_out, int out_size) {
    const int*   inputs = nullptr;
    const float* ua     = nullptr;
    const float* nth    = nullptr;
    for (int i = 0; i < n_in; i++) {
        if (in_sizes[i] == 3456)      inputs = (const int*)d_in[i];
        else if (in_sizes[i] == 20)   ua     = (const float*)d_in[i];
        else if (in_sizes[i] == 220)  nth    = (const float*)d_in[i];
    }
    rvqe_kernel<<<64, NTH>>>(inputs, ua, nth, (float*)d_out, out_size);
}

// round 14
// speedup vs baseline: 1.1801x; 1.1801x over previous
#include <cuda_runtime.h>
#include <math.h>
#include <stdint.h>

// RVQE: 12-qubit real statevector recurrent cell, B=64, T=9 (8 scan steps).
// One CTA per batch element; state = 4096 floats = 256 threads x 8 packed f32x2.
// Global amplitude index g12 (12 bits), g12 = (t << 4) | r:
//   r bits: bit0=lane11(anc1), bit1=lane10(anc0), bit2=lane9(PACKED), bit3=lane8
//   t bits 0..4 (warp lane): lanes 7,6,5,4,3  -> __shfl_xor (mask 1<<(7-lane))
//   t bits 5,6,7: lanes 2,1,0 -> smem exchange
// PACKING: P[j], j = a*4 + i, i = (anc0<<1)|anc1, a = lane8 bit.
//   P[j].lo = lane9=0, P[j].hi = lane9=1.
//
// Fused neuron algebra (validated rounds 3/5/8): per stage
//   chain = E(a_0) C_0 G_0 T'(D1) C_1 G_1 ... T'(D9) C_9 G_9 F(a_9)
//
// SPARSITY EXPLOIT: after projection the state is the product
// |j>_{lanes0..5} (x) phi, phi = 64 floats. Steps start from compressed phi in
// smem: every thread reconstructs P = sigma_t * invn * phi[chunk], where
// sigma_t = prod_{l=0..5} r_l(x_l; j_l) is the scalar effect of ALL stage-0
// RYs on lanes 0..5 applied to basis |j>. This removes stage-0's two smem RY
// exchanges, three shfl-RY rounds, and the project/zero/scale pass.
// Exchanges ping-pong A/B with one sync each; 9 syncs/step.

namespace {

typedef unsigned long long u64;

constexpr int NTH   = 256;
constexpr int TT    = 9;
constexpr int NSTEP = 8;
constexpr int NIDX  = 22;   // 18 deltas + 2 entries + 2 trailings
constexpr int STq   = 9;    // exch stride in u64 (8 + 1 pad; odd -> conflict-free)
constexpr u64 SGN2  = 0x8000000080000000ULL;

__device__ __forceinline__ u64 pk(float lo, float hi) {
    u64 r; asm("mov.b64 %0,{%1,%2};" : "=l"(r) : "f"(lo), "f"(hi)); return r;
}
__device__ __forceinline__ void upk(u64 u, float& lo, float& hi) {
    asm("mov.b64 {%0,%1},%2;" : "=f"(lo), "=f"(hi) : "l"(u));
}
__device__ __forceinline__ u64 bc(float x) { return pk(x, x); }
__device__ __forceinline__ u64 f2mul(u64 a, u64 b) {
    u64 d; asm("mul.rn.f32x2 %0,%1,%2;" : "=l"(d) : "l"(a), "l"(b)); return d;
}
__device__ __forceinline__ u64 f2fma(u64 a, u64 b, u64 c) {
    u64 d; asm("fma.rn.f32x2 %0,%1,%2,%3;" : "=l"(d) : "l"(a), "l"(b), "l"(c)); return d;
}
__device__ __forceinline__ u64 f2neg(u64 a) { return a ^ SGN2; }
__device__ __forceinline__ u64 f2swap(u64 a) { float lo, hi; upk(a, lo, hi); return pk(hi, lo); }

// ---- stage RY pieces ----

__device__ __forceinline__ void ry_lane9(u64* P, u64 C, u64 SW) {
#pragma unroll
    for (int j = 0; j < 8; j++)
        P[j] = f2fma(SW, f2swap(P[j]), f2mul(C, P[j]));
}

__device__ __forceinline__ void ry_lane8(u64* P, float c, float s) {
    u64 C = bc(c), S = bc(s), NS = bc(-s);
#pragma unroll
    for (int i = 0; i < 4; i++) {
        u64 u = P[i], w = P[4 + i];
        P[i]     = f2fma(NS, w, f2mul(C, u));
        P[4 + i] = f2fma(S,  u, f2mul(C, w));
    }
}

__device__ __forceinline__ void ry_shfl(u64* P, int t, int m, float c, float s) {
    u64 C = bc(c), SE = bc((t & m) ? s : -s);
#pragma unroll
    for (int j = 0; j < 8; j++) {
        u64 w = __shfl_xor_sync(0xffffffffu, P[j], m);
        P[j] = f2fma(SE, w, f2mul(C, P[j]));
    }
}

// Combined RY(lane0)*RY(lane1) (t bits 7,6): one sync, 4-way gather.
__device__ __forceinline__ void ry_smem4(u64* P, int t,
                                         float c0, float s0, float c1, float s1,
                                         u64* X) {
#pragma unroll
    for (int j = 0; j < 8; j++) X[t * STq + j] = P[j];
    __syncthreads();
    int a  = (t >> 7) & 1;
    int bb = (t >> 6) & 1;
    float r0a0 = a  ? s0 : c0;
    float r0a1 = a  ? c0 : -s0;
    float r1b0 = bb ? s1 : c1;
    float r1b1 = bb ? c1 : -s1;
    u64 k00 = bc(r0a0 * r1b0), k01 = bc(r0a0 * r1b1);
    u64 k10 = bc(r0a1 * r1b0), k11 = bc(r0a1 * r1b1);
    int base = t & 63;
    const u64* x00 = X + base * STq;
    const u64* x01 = X + (base | 64)  * STq;
    const u64* x10 = X + (base | 128) * STq;
    const u64* x11 = X + (base | 192) * STq;
#pragma unroll
    for (int j = 0; j < 8; j++)
        P[j] = f2fma(k00, x00[j],
               f2fma(k01, x01[j],
               f2fma(k10, x10[j], f2mul(k11, x11[j]))));
    // no trailing sync: ping-pong ordering
}

// RY on lane2 (t bit5): 2-way exchange, one sync.
__device__ __forceinline__ void ry_smem1(u64* P, int t, float c, float s, u64* X) {
#pragma unroll
    for (int j = 0; j < 8; j++) X[t * STq + j] = P[j];
    __syncthreads();
    const u64* xp = X + (t ^ 32) * STq;
    u64 C = bc(c), SE = bc((t & 32) ? s : -s);
#pragma unroll
    for (int j = 0; j < 8; j++) P[j] = f2fma(SE, xp[j], f2mul(C, P[j]));
    // no trailing sync: ping-pong ordering
}

// ---- CiY pieces (ctrl anc1: odd j) ----

__device__ __forceinline__ void ciy_lane9(u64* P) {
#pragma unroll
    for (int j = 1; j < 8; j += 2) {
        float lo, hi; upk(P[j], lo, hi);
        P[j] = pk(hi, -lo);
    }
}

__device__ __forceinline__ void ciy_lane8(u64* P) {
#pragma unroll
    for (int i = 1; i < 4; i += 2) {
        u64 p0 = P[i];
        P[i] = P[4 + i];
        P[4 + i] = f2neg(p0);
    }
}

__device__ __forceinline__ void ciy_shfl(u64* P, int t, int m) {
    u64 sgn = (t & m) ? SGN2 : 0ULL;
#pragma unroll
    for (int j = 1; j < 8; j += 2) {
        u64 w = __shfl_xor_sync(0xffffffffu, P[j], m);
        P[j] = w ^ sgn;
    }
}

// Cross-warp CiY: one sync, ping-pong buffer.
__device__ __forceinline__ void ciy_smem(u64* P, int t, int m, u64* X) {
#pragma unroll
    for (int j = 1; j < 8; j += 2) X[t * STq + (j >> 1)] = P[j];
    __syncthreads();
    const u64* p = X + (t ^ m) * STq;
    u64 sgn = (t & m) ? SGN2 : 0ULL;
#pragma unroll
    for (int j = 1; j < 8; j += 2) P[j] = p[j >> 1] ^ sgn;
    // no trailing sync: ping-pong ordering
}

// ---- fused neuron ops (packed over lane9; loop over a = lane8 bit) ----
// x_i = P[a*4+i]: x0=(0,0) x1=(0,1) x2=(1,0) x3=(1,1) of (anc0,anc1)

__device__ __forceinline__ void applyT(u64* P, float cb, float sb,
                                       const u64* DC, const u64* DS) {
    u64 CB = bc(cb), SB = bc(sb), NSB = bc(-sb);
#pragma unroll
    for (int a = 0; a < 2; a++) {
        u64 C  = f2fma(NSB, DS[a], f2mul(CB, DC[a]));
        u64 S  = f2fma(SB,  DC[a], f2mul(CB, DS[a]));
        u64 NS = f2neg(S);
        u64 x0 = P[4*a+0], x1 = P[4*a+1], x2 = P[4*a+2], x3 = P[4*a+3];
        P[4*a+0] = f2fma(S,  x3, f2mul(C, x0));
        P[4*a+1] = f2fma(NS, x2, f2mul(C, x1));
        P[4*a+2] = f2fma(S,  x1, f2mul(C, x2));
        P[4*a+3] = f2fma(NS, x0, f2mul(C, x3));
    }
}

__device__ __forceinline__ void applyE(u64* P, float cb, float sb,
                                       const u64* DC, const u64* DS) {
    u64 CB = bc(cb), SB = bc(sb), NSB = bc(-sb);
#pragma unroll
    for (int a = 0; a < 2; a++) {
        u64 C  = f2fma(NSB, DS[a], f2mul(CB, DC[a]));
        u64 S  = f2fma(SB,  DC[a], f2mul(CB, DS[a]));
        u64 NS = f2neg(S);
        u64 x0 = P[4*a+0], x1 = P[4*a+1], x2 = P[4*a+2], x3 = P[4*a+3];
        P[4*a+0] = f2fma(NS, x2, f2mul(C, x0));
        P[4*a+1] = f2fma(NS, x3, f2mul(C, x1));
        P[4*a+2] = f2fma(S,  x1, f2mul(C, x3));
        P[4*a+3] = f2neg(f2fma(S, x0, f2mul(C, x2)));
    }
}

__device__ __forceinline__ void applyF(u64* P, float cb, float sb,
                                       const u64* DC, const u64* DS) {
    u64 CB = bc(cb), SB = bc(sb), NSB = bc(-sb);
#pragma unroll
    for (int a = 0; a < 2; a++) {
        u64 C  = f2fma(NSB, DS[a], f2mul(CB, DC[a]));
        u64 S  = f2fma(SB,  DC[a], f2mul(CB, DS[a]));
        u64 NS = f2neg(S);
        u64 x0 = P[4*a+0], x1 = P[4*a+1], x2 = P[4*a+2], x3 = P[4*a+3];
        P[4*a+0] = f2fma(NS, x3, f2mul(C, x0));
        P[4*a+1] = f2fma(S,  x2, f2mul(C, x1));
        P[4*a+2] = f2neg(f2fma(S, x0, f2mul(C, x3)));
        P[4*a+3] = f2fma(NS, x1, f2mul(C, x2));
    }
}

__device__ __forceinline__ void applyG_se(u64* P, u64 C, u64 SE0, u64 SE1) {
    u64 NSE0 = f2neg(SE0), NSE1 = f2neg(SE1);
    {
        u64 x1 = P[1], x3 = P[3];
        P[1] = f2fma(NSE0, x3, f2mul(C, x1));
        P[3] = f2fma(SE0,  x1, f2mul(C, x3));
    }
    {
        u64 x1 = P[5], x3 = P[7];
        P[5] = f2fma(NSE1, x3, f2mul(C, x1));
        P[7] = f2fma(SE1,  x1, f2mul(C, x3));
    }
}

// angle-vector spec tables
__device__ constexpr int aIdx[NIDX] = {1,2,3,4,5,6,7,8,9, 11,12,13,14,15,16,17,18,19, 0, 10, 9, 19};
__device__ constexpr int bIdx[NIDX] = {0,1,2,3,4,5,6,7,8, 10,11,12,13,14,15,16,17,18, -1,-1,-1,-1};

__global__ void __launch_bounds__(NTH, 1) rvqe_kernel(
    const int*   __restrict__ inputs,   // (64, 9, 6) int32
    const float* __restrict__ ua,       // (2, 10)
    const float* __restrict__ nth,      // (2, 10, 11)
    float*       __restrict__ out,
    int out_size)
{
    __shared__ u64   bufA[NTH * STq];   // 18432 B
    __shared__ u64   bufB[NTH * STq];   // 18432 B
    __shared__ u64   phi[32];           // compressed state (64 floats)
    __shared__ float uc[20], us[20];
    __shared__ u64   DC2[NIDX][2], DS2[NIDX][2];
    __shared__ float gc_sm[20], gs_sm[20];
    __shared__ u64   se9p[2];
    __shared__ float probs_sm[64];
    __shared__ int   tIdx[TT];

    const int t = threadIdx.x;
    const int b = blockIdx.x;
    const int* inb = inputs + b * TT * 6;

    // ---- precompute ----
    if (t < 20) {
        float c, s; sincosf(0.5f * ua[t], &s, &c);
        uc[t] = c; us[t] = s;
        float cg, sg; sincosf(0.5f * nth[t * 11 + (t % 10)], &sg, &cg);
        gc_sm[t] = cg; gs_sm[t] = sg;
        if ((t % 10) == 9) se9p[t / 10] = pk(-sg, sg);
    }
    if (t < NIDX * 2) {
        int idx = t >> 1, a = t & 1;
        const float* A = nth + aIdx[idx] * 11;
        const float* Bp = (bIdx[idx] >= 0) ? (nth + bIdx[idx] * 11) : nullptr;
        float d8 = A[8] - (Bp ? Bp[8] : 0.f);
        float d9 = A[9] - (Bp ? Bp[9] : 0.f);
        float dlo = a ? d8 : 0.f;
        float dhi = dlo + d9;
        float cl, sl, ch, sh;
        sincosf(0.5f * dlo, &sl, &cl);
        sincosf(0.5f * dhi, &sh, &ch);
        DC2[idx][a] = pk(cl, ch);
        DS2[idx][a] = pk(sl, sh);
    }
    if (t < TT) {
        int idx = 0;
#pragma unroll
        for (int i = 0; i < 6; i++) idx |= (inb[t * 6 + i] & 1) << (5 - i);
        tIdx[t] = idx;
    }
    // init compressed state: phi = e0 (|0...0> on lanes 6..11), probs = 1
    if (t < 64) probs_sm[t] = 1.0f;
    if (t < 32) phi[t] = 0ULL;
    if (t == 0) phi[0] = pk(1.f, 0.f);

    // per-thread base trig in REGISTERS (lane i -> t bit (7-i), i=0..7)
    float cbs[NIDX], sbs[NIDX];
#pragma unroll
    for (int idx = 0; idx < NIDX; idx++) {
        const float* A = nth + aIdx[idx] * 11;
        const float* Bp = (bIdx[idx] >= 0) ? (nth + bIdx[idx] * 11) : nullptr;
        float base = A[10] - (Bp ? Bp[10] : 0.f);
#pragma unroll
        for (int i = 0; i < 8; i++)
            if ((t >> (7 - i)) & 1) base += A[i] - (Bp ? Bp[i] : 0.f);
        float c, s; sincosf(0.5f * base, &s, &c);
        cbs[idx] = c; sbs[idx] = s;
    }
    __syncthreads();

    u64 P[8];

    for (int step = 0; step < NSTEP; step++) {
        // ---- prologue: reconstruct from compressed phi ----
        // state entering step is |j>_{lanes0..5} (x) phi; stage-0 RYs on
        // lanes 0..5 applied to basis |j> give the scalar sigma_t.
        {
            int j = tIdx[step];
            float prod = 1.0f / sqrtf(probs_sm[j]);
#pragma unroll
            for (int l = 0; l < 6; l++) {
                int x  = (t >> (7 - l)) & 1;
                int jl = (j >> (5 - l)) & 1;
                float f = (x == jl) ? uc[l] : (x ? us[l] : -us[l]);
                prod *= f;
            }
            u64 SIG = bc(prod);
            int pb = (t & 3) * 8;
#pragma unroll
            for (int jj = 0; jj < 8; jj++) P[jj] = f2mul(SIG, phi[pb + jj]);
        }

        // ======== stage 0 ========
        {
            const float* ucc = uc;
            const float* uss = us;
            // remaining stage-0 RYs: lanes 6,7 shfl; lane8 cross-reg; lane9 packed
            ry_lane8(P, ucc[8], uss[8]);
            {
                u64 C9 = bc(ucc[9]);
                u64 SW = pk(-uss[9], uss[9]);
                ry_lane9(P, C9, SW);
            }
            ry_shfl(P, t, 2, ucc[6], uss[6]);
            ry_shfl(P, t, 1, ucc[7], uss[7]);

            // neuron chain: E C0 G0 T' C1 G1 ... T' C9 G9 F
            applyE(P, cbs[18], sbs[18], DC2[18], DS2[18]);
            ciy_smem(P, t, 128, bufA);                 // C0
            {
                float sg = ((t >> 7) & 1) ? gs_sm[0] : -gs_sm[0];
                u64 SE = bc(sg);
                applyG_se(P, bc(gc_sm[0]), SE, SE);
            }
#pragma unroll
            for (int n = 1; n < 10; n++) {
                int di = n - 1;
                applyT(P, cbs[di], sbs[di], DC2[di], DS2[di]);
                if (n == 9)      ciy_lane9(P);
                else if (n == 8) ciy_lane8(P);
                else if (n >= 3) ciy_shfl(P, t, 1 << (7 - n));
                else if (n == 1) ciy_smem(P, t, 64, bufB);
                else             ciy_smem(P, t, 32, bufA);
                u64 C = bc(gc_sm[n]);
                if (n <= 7) {
                    float sg = ((t >> (7 - n)) & 1) ? gs_sm[n] : -gs_sm[n];
                    u64 SE = bc(sg);
                    applyG_se(P, C, SE, SE);
                } else if (n == 8) {
                    u64 SE1 = bc(gs_sm[n]);
                    applyG_se(P, C, f2neg(SE1), SE1);
                } else {
                    applyG_se(P, C, se9p[0], se9p[0]);
                }
            }
            applyF(P, cbs[20], sbs[20], DC2[20], DS2[20]);
        }

        // ======== stage 1 (full) ========
        {
            const float* ucc = uc + 10;
            const float* uss = us + 10;
            ry_lane8(P, ucc[8], uss[8]);
            {
                u64 C9 = bc(ucc[9]);
                u64 SW = pk(-uss[9], uss[9]);
                ry_lane9(P, C9, SW);
            }
#pragma unroll
            for (int l = 3; l <= 7; l++)
                ry_shfl(P, t, 1 << (7 - l), ucc[l], uss[l]);
            ry_smem4(P, t, ucc[0], uss[0], ucc[1], uss[1], bufB);
            ry_smem1(P, t, ucc[2], uss[2], bufA);

            applyE(P, cbs[19], sbs[19], DC2[19], DS2[19]);
            ciy_smem(P, t, 128, bufB);                 // C0
            {
                float sg = ((t >> 7) & 1) ? gs_sm[10] : -gs_sm[10];
                u64 SE = bc(sg);
                applyG_se(P, bc(gc_sm[10]), SE, SE);
            }
#pragma unroll
            for (int n = 1; n < 10; n++) {
                int di = 9 + n - 1;
                applyT(P, cbs[di], sbs[di], DC2[di], DS2[di]);
                if (n == 9)      ciy_lane9(P);
                else if (n == 8) ciy_lane8(P);
                else if (n >= 3) ciy_shfl(P, t, 1 << (7 - n));
                else if (n == 1) ciy_smem(P, t, 64, bufA);
                else             ciy_smem(P, t, 32, bufB);
                int gi = 10 + n;
                u64 C = bc(gc_sm[gi]);
                if (n <= 7) {
                    float sg = ((t >> (7 - n)) & 1) ? gs_sm[gi] : -gs_sm[gi];
                    u64 SE = bc(sg);
                    applyG_se(P, C, SE, SE);
                } else if (n == 8) {
                    u64 SE1 = bc(gs_sm[gi]);
                    applyG_se(P, C, f2neg(SE1), SE1);
                } else {
                    applyG_se(P, C, se9p[1], se9p[1]);
                }
            }
            applyF(P, cbs[21], sbs[21], DC2[21], DS2[21]);
        }

        // ---- probs + compress (replaces project/zero/scale) ----
        u64 acc = 0ULL;
#pragma unroll
        for (int j = 0; j < 8; j++) acc = f2fma(P[j], P[j], acc);
        float alo, ahi; upk(acc, alo, ahi);
        float ssq = alo + ahi;
        ssq += __shfl_xor_sync(0xffffffffu, ssq, 1);
        ssq += __shfl_xor_sync(0xffffffffu, ssq, 2);
        if (!(t & 3)) {
            probs_sm[t >> 2] = ssq;
            out[(b * NSTEP + step) * 64 + (t >> 2)] = ssq;
        }
        // holders of the projected component store compressed phi (RAW;
        // normalization is folded into next step's sigma)
        if ((t >> 2) == tIdx[step + 1]) {
            int pb = (t & 3) * 8;
#pragma unroll
            for (int jj = 0; jj < 8; jj++) phi[pb + jj] = P[jj];
        }
        __syncthreads();
    }

    // ---- second tuple output: measured = inputs[:,1:] as float ----
    if (out_size > 32768 && t < 48) {
        out[32768 + b * 48 + t] = (float)inb[6 + t];
    }
}

} // namespace

extern "C" void kernel_launch(void* const* d_in, const int* in_sizes, int n_in,
                              void* d_out, int out_size) {
    const int*   inputs = nullptr;
    const float* ua     = nullptr;
    const float* nth    = nullptr;
    for (int i = 0; i < n_in; i++) {
        if (in_sizes[i] == 3456)      inputs = (const int*)d_in[i];
        else if (in_sizes[i] == 20)   ua     = (const float*)d_in[i];
        else if (in_sizes[i] == 220)  nth    = (const float*)d_in[i];
    }
    rvqe_kernel<<<64, NTH>>>(inputs, ua, nth, (float*)d_out, out_size);
}

// round 15
// speedup vs baseline: 1.1844x; 1.0037x over previous
#include <cuda_runtime.h>
#include <math.h>
#include <stdint.h>

// RVQE: 12-qubit real statevector recurrent cell, B=64, T=9 (8 scan steps).
// One CTA per batch element; state = 4096 floats = 256 threads x 8 packed f32x2.
// Global amplitude index g12 (12 bits), g12 = (t << 4) | r:
//   r bits: bit0=lane11(anc1), bit1=lane10(anc0), bit2=lane9(PACKED), bit3=lane8
//   t bits 0..4 (warp lane): lanes 7,6,5,4,3  -> __shfl_xor (mask 1<<(7-lane))
//   t bits 5,6,7: lanes 2,1,0 -> smem exchange
// PACKING: P[j], j = a*4 + i, i = (anc0<<1)|anc1, a = lane8 bit.
//   P[j].lo = lane9=0, P[j].hi = lane9=1.
//
// Fused neuron algebra (validated rounds 3/5/8): per stage
//   chain = E(a_0) C_0 G_0 T'(D1) C_1 G_1 ... T'(D9) C_9 G_9 F(a_9)
//
// SPARSITY EXPLOIT (validated round 14): steps start from compressed phi;
// P = sigma_t * invn * phi[chunk] replaces stage-0 lane0..5 RYs + projection.
//
// NEW (this round): the T' rotation coefficients (C,S per thread per delta per
// a-group) are STEP-INVARIANT. Precompute once into a per-thread smem table
// (stride 73 u64; 73 mod 16 = 9, coprime -> conflict-free LDS.64). applyT
// becomes 4 loads + 16 FMAs (was: 4 loads + 8 coef f2 + 16 FMAs), removing
// ~13% of the f2 stream and the coef dependency stage from every neuron.

namespace {

typedef unsigned long long u64;

constexpr int NTH   = 256;
constexpr int TT    = 9;
constexpr int NSTEP = 8;
constexpr int NIDX  = 22;   // 18 deltas + 2 entries + 2 trailings
constexpr int STq   = 9;    // exch stride in u64 (8 + 1 pad; odd -> conflict-free)
constexpr int CSW   = 73;   // coef table per-thread stride in u64 (72 + 1 pad)
constexpr u64 SGN2  = 0x8000000080000000ULL;

// dynamic smem layout (u64 units)
constexpr int OFF_A   = 0;
constexpr int OFF_B   = NTH * STq;        // 2304
constexpr int OFF_TAB = OFF_B + NTH * STq; // 4608
constexpr int DYN_U64 = OFF_TAB + NTH * CSW; // 4608 + 18688 = 23296 -> 186368 B

__device__ __forceinline__ u64 pk(float lo, float hi) {
    u64 r; asm("mov.b64 %0,{%1,%2};" : "=l"(r) : "f"(lo), "f"(hi)); return r;
}
__device__ __forceinline__ void upk(u64 u, float& lo, float& hi) {
    asm("mov.b64 {%0,%1},%2;" : "=f"(lo), "=f"(hi) : "l"(u));
}
__device__ __forceinline__ u64 bc(float x) { return pk(x, x); }
__device__ __forceinline__ u64 f2mul(u64 a, u64 b) {
    u64 d; asm("mul.rn.f32x2 %0,%1,%2;" : "=l"(d) : "l"(a), "l"(b)); return d;
}
__device__ __forceinline__ u64 f2fma(u64 a, u64 b, u64 c) {
    u64 d; asm("fma.rn.f32x2 %0,%1,%2,%3;" : "=l"(d) : "l"(a), "l"(b), "l"(c)); return d;
}
__device__ __forceinline__ u64 f2neg(u64 a) { return a ^ SGN2; }
__device__ __forceinline__ u64 f2swap(u64 a) { float lo, hi; upk(a, lo, hi); return pk(hi, lo); }

// ---- stage RY pieces ----

__device__ __forceinline__ void ry_lane9(u64* P, u64 C, u64 SW) {
#pragma unroll
    for (int j = 0; j < 8; j++)
        P[j] = f2fma(SW, f2swap(P[j]), f2mul(C, P[j]));
}

__device__ __forceinline__ void ry_lane8(u64* P, float c, float s) {
    u64 C = bc(c), S = bc(s), NS = bc(-s);
#pragma unroll
    for (int i = 0; i < 4; i++) {
        u64 u = P[i], w = P[4 + i];
        P[i]     = f2fma(NS, w, f2mul(C, u));
        P[4 + i] = f2fma(S,  u, f2mul(C, w));
    }
}

__device__ __forceinline__ void ry_shfl(u64* P, int t, int m, float c, float s) {
    u64 C = bc(c), SE = bc((t & m) ? s : -s);
#pragma unroll
    for (int j = 0; j < 8; j++) {
        u64 w = __shfl_xor_sync(0xffffffffu, P[j], m);
        P[j] = f2fma(SE, w, f2mul(C, P[j]));
    }
}

// Combined RY(lane0)*RY(lane1) (t bits 7,6): one sync, 4-way gather.
__device__ __forceinline__ void ry_smem4(u64* P, int t,
                                         float c0, float s0, float c1, float s1,
                                         u64* X) {
#pragma unroll
    for (int j = 0; j < 8; j++) X[t * STq + j] = P[j];
    __syncthreads();
    int a  = (t >> 7) & 1;
    int bb = (t >> 6) & 1;
    float r0a0 = a  ? s0 : c0;
    float r0a1 = a  ? c0 : -s0;
    float r1b0 = bb ? s1 : c1;
    float r1b1 = bb ? c1 : -s1;
    u64 k00 = bc(r0a0 * r1b0), k01 = bc(r0a0 * r1b1);
    u64 k10 = bc(r0a1 * r1b0), k11 = bc(r0a1 * r1b1);
    int base = t & 63;
    const u64* x00 = X + base * STq;
    const u64* x01 = X + (base | 64)  * STq;
    const u64* x10 = X + (base | 128) * STq;
    const u64* x11 = X + (base | 192) * STq;
#pragma unroll
    for (int j = 0; j < 8; j++)
        P[j] = f2fma(k00, x00[j],
               f2fma(k01, x01[j],
               f2fma(k10, x10[j], f2mul(k11, x11[j]))));
    // no trailing sync: ping-pong ordering
}

// RY on lane2 (t bit5): 2-way exchange, one sync.
__device__ __forceinline__ void ry_smem1(u64* P, int t, float c, float s, u64* X) {
#pragma unroll
    for (int j = 0; j < 8; j++) X[t * STq + j] = P[j];
    __syncthreads();
    const u64* xp = X + (t ^ 32) * STq;
    u64 C = bc(c), SE = bc((t & 32) ? s : -s);
#pragma unroll
    for (int j = 0; j < 8; j++) P[j] = f2fma(SE, xp[j], f2mul(C, P[j]));
    // no trailing sync: ping-pong ordering
}

// ---- CiY pieces (ctrl anc1: odd j) ----

__device__ __forceinline__ void ciy_lane9(u64* P) {
#pragma unroll
    for (int j = 1; j < 8; j += 2) {
        float lo, hi; upk(P[j], lo, hi);
        P[j] = pk(hi, -lo);
    }
}

__device__ __forceinline__ void ciy_lane8(u64* P) {
#pragma unroll
    for (int i = 1; i < 4; i += 2) {
        u64 p0 = P[i];
        P[i] = P[4 + i];
        P[4 + i] = f2neg(p0);
    }
}

__device__ __forceinline__ void ciy_shfl(u64* P, int t, int m) {
    u64 sgn = (t & m) ? SGN2 : 0ULL;
#pragma unroll
    for (int j = 1; j < 8; j += 2) {
        u64 w = __shfl_xor_sync(0xffffffffu, P[j], m);
        P[j] = w ^ sgn;
    }
}

// Cross-warp CiY: one sync, ping-pong buffer.
__device__ __forceinline__ void ciy_smem(u64* P, int t, int m, u64* X) {
#pragma unroll
    for (int j = 1; j < 8; j += 2) X[t * STq + (j >> 1)] = P[j];
    __syncthreads();
    const u64* p = X + (t ^ m) * STq;
    u64 sgn = (t & m) ? SGN2 : 0ULL;
#pragma unroll
    for (int j = 1; j < 8; j += 2) P[j] = p[j >> 1] ^ sgn;
    // no trailing sync: ping-pong ordering
}

// ---- fused neuron ops (packed over lane9; loop over a = lane8 bit) ----
// x_i = P[a*4+i]: x0=(0,0) x1=(0,1) x2=(1,0) x3=(1,1) of (anc0,anc1)

// T' with precomputed coefficients: cs = {C0,S0,C1,S1} in the per-thread table.
__device__ __forceinline__ void applyT_tab(u64* P, const u64* cs) {
#pragma unroll
    for (int a = 0; a < 2; a++) {
        u64 C  = cs[a * 2 + 0];
        u64 S  = cs[a * 2 + 1];
        u64 NS = f2neg(S);
        u64 x0 = P[4*a+0], x1 = P[4*a+1], x2 = P[4*a+2], x3 = P[4*a+3];
        P[4*a+0] = f2fma(S,  x3, f2mul(C, x0));
        P[4*a+1] = f2fma(NS, x2, f2mul(C, x1));
        P[4*a+2] = f2fma(S,  x1, f2mul(C, x2));
        P[4*a+3] = f2fma(NS, x0, f2mul(C, x3));
    }
}

__device__ __forceinline__ void applyE(u64* P, float cb, float sb,
                                       const u64* DC, const u64* DS) {
    u64 CB = bc(cb), SB = bc(sb), NSB = bc(-sb);
#pragma unroll
    for (int a = 0; a < 2; a++) {
        u64 C  = f2fma(NSB, DS[a], f2mul(CB, DC[a]));
        u64 S  = f2fma(SB,  DC[a], f2mul(CB, DS[a]));
        u64 NS = f2neg(S);
        u64 x0 = P[4*a+0], x1 = P[4*a+1], x2 = P[4*a+2], x3 = P[4*a+3];
        P[4*a+0] = f2fma(NS, x2, f2mul(C, x0));
        P[4*a+1] = f2fma(NS, x3, f2mul(C, x1));
        P[4*a+2] = f2fma(S,  x1, f2mul(C, x3));
        P[4*a+3] = f2neg(f2fma(S, x0, f2mul(C, x2)));
    }
}

__device__ __forceinline__ void applyF(u64* P, float cb, float sb,
                                       const u64* DC, const u64* DS) {
    u64 CB = bc(cb), SB = bc(sb), NSB = bc(-sb);
#pragma unroll
    for (int a = 0; a < 2; a++) {
        u64 C  = f2fma(NSB, DS[a], f2mul(CB, DC[a]));
        u64 S  = f2fma(SB,  DC[a], f2mul(CB, DS[a]));
        u64 NS = f2neg(S);
        u64 x0 = P[4*a+0], x1 = P[4*a+1], x2 = P[4*a+2], x3 = P[4*a+3];
        P[4*a+0] = f2fma(NS, x3, f2mul(C, x0));
        P[4*a+1] = f2fma(S,  x2, f2mul(C, x1));
        P[4*a+2] = f2neg(f2fma(S, x0, f2mul(C, x3)));
        P[4*a+3] = f2fma(NS, x1, f2mul(C, x2));
    }
}

__device__ __forceinline__ void applyG_se(u64* P, u64 C, u64 SE0, u64 SE1) {
    u64 NSE0 = f2neg(SE0), NSE1 = f2neg(SE1);
    {
        u64 x1 = P[1], x3 = P[3];
        P[1] = f2fma(NSE0, x3, f2mul(C, x1));
        P[3] = f2fma(SE0,  x1, f2mul(C, x3));
    }
    {
        u64 x1 = P[5], x3 = P[7];
        P[5] = f2fma(NSE1, x3, f2mul(C, x1));
        P[7] = f2fma(SE1,  x1, f2mul(C, x3));
    }
}

// angle-vector spec tables
__device__ constexpr int aIdx[NIDX] = {1,2,3,4,5,6,7,8,9, 11,12,13,14,15,16,17,18,19, 0, 10, 9, 19};
__device__ constexpr int bIdx[NIDX] = {0,1,2,3,4,5,6,7,8, 10,11,12,13,14,15,16,17,18, -1,-1,-1,-1};

__global__ void __launch_bounds__(NTH, 1) rvqe_kernel(
    const int*   __restrict__ inputs,   // (64, 9, 6) int32
    const float* __restrict__ ua,       // (2, 10)
    const float* __restrict__ nth,      // (2, 10, 11)
    float*       __restrict__ out,
    int out_size)
{
    extern __shared__ u64 dyn[];
    u64* bufA = dyn + OFF_A;
    u64* bufB = dyn + OFF_B;
    u64* tab  = dyn + OFF_TAB;          // per-thread coef rows, stride CSW

    __shared__ u64   phi[32];           // compressed state (64 floats)
    __shared__ float uc[20], us[20];
    __shared__ u64   DC2[NIDX][2], DS2[NIDX][2];
    __shared__ float gc_sm[20], gs_sm[20];
    __shared__ u64   se9p[2];
    __shared__ float probs_sm[64];
    __shared__ int   tIdx[TT];

    const int t = threadIdx.x;
    const int b = blockIdx.x;
    const int* inb = inputs + b * TT * 6;

    // ---- precompute (phase 1: shared tables) ----
    if (t < 20) {
        float c, s; sincosf(0.5f * ua[t], &s, &c);
        uc[t] = c; us[t] = s;
        float cg, sg; sincosf(0.5f * nth[t * 11 + (t % 10)], &sg, &cg);
        gc_sm[t] = cg; gs_sm[t] = sg;
        if ((t % 10) == 9) se9p[t / 10] = pk(-sg, sg);
    }
    if (t < NIDX * 2) {
        int idx = t >> 1, a = t & 1;
        const float* A = nth + aIdx[idx] * 11;
        const float* Bp = (bIdx[idx] >= 0) ? (nth + bIdx[idx] * 11) : nullptr;
        float d8 = A[8] - (Bp ? Bp[8] : 0.f);
        float d9 = A[9] - (Bp ? Bp[9] : 0.f);
        float dlo = a ? d8 : 0.f;
        float dhi = dlo + d9;
        float cl, sl, ch, sh;
        sincosf(0.5f * dlo, &sl, &cl);
        sincosf(0.5f * dhi, &sh, &ch);
        DC2[idx][a] = pk(cl, ch);
        DS2[idx][a] = pk(sl, sh);
    }
    if (t < TT) {
        int idx = 0;
#pragma unroll
        for (int i = 0; i < 6; i++) idx |= (inb[t * 6 + i] & 1) << (5 - i);
        tIdx[t] = idx;
    }
    // init compressed state: phi = e0 (|0...0> on lanes 6..11), probs = 1
    if (t < 64) probs_sm[t] = 1.0f;
    if (t < 32) phi[t] = 0ULL;
    if (t == 0) phi[0] = pk(1.f, 0.f);
    __syncthreads();

    // ---- precompute (phase 2): per-thread base trig; T-coef table for idx<18;
    //      E/F (idx 18..21) keep register base trig ----
    float cbs4[4], sbs4[4];
    {
        u64* row = tab + t * CSW;
#pragma unroll
        for (int idx = 0; idx < NIDX; idx++) {
            const float* A = nth + aIdx[idx] * 11;
            const float* Bp = (bIdx[idx] >= 0) ? (nth + bIdx[idx] * 11) : nullptr;
            float base = A[10] - (Bp ? Bp[10] : 0.f);
#pragma unroll
            for (int i = 0; i < 8; i++)
                if ((t >> (7 - i)) & 1) base += A[i] - (Bp ? Bp[i] : 0.f);
            float c, s; sincosf(0.5f * base, &s, &c);
            if (idx < 18) {
                u64 CB = bc(c), SB = bc(s), NSB = bc(-s);
#pragma unroll
                for (int a = 0; a < 2; a++) {
                    u64 C = f2fma(NSB, DS2[idx][a], f2mul(CB, DC2[idx][a]));
                    u64 S = f2fma(SB,  DC2[idx][a], f2mul(CB, DS2[idx][a]));
                    row[idx * 4 + a * 2 + 0] = C;
                    row[idx * 4 + a * 2 + 1] = S;
                }
            } else {
                cbs4[idx - 18] = c; sbs4[idx - 18] = s;
            }
        }
    }
    __syncthreads();

    const u64* myCS = tab + t * CSW;
    u64 P[8];

    for (int step = 0; step < NSTEP; step++) {
        // ---- prologue: reconstruct from compressed phi ----
        {
            int j = tIdx[step];
            float prod = 1.0f / sqrtf(probs_sm[j]);
#pragma unroll
            for (int l = 0; l < 6; l++) {
                int x  = (t >> (7 - l)) & 1;
                int jl = (j >> (5 - l)) & 1;
                float f = (x == jl) ? uc[l] : (x ? us[l] : -us[l]);
                prod *= f;
            }
            u64 SIG = bc(prod);
            int pb = (t & 3) * 8;
#pragma unroll
            for (int jj = 0; jj < 8; jj++) P[jj] = f2mul(SIG, phi[pb + jj]);
        }

        // ======== stage 0 ========
        {
            const float* ucc = uc;
            const float* uss = us;
            ry_lane8(P, ucc[8], uss[8]);
            {
                u64 C9 = bc(ucc[9]);
                u64 SW = pk(-uss[9], uss[9]);
                ry_lane9(P, C9, SW);
            }
            ry_shfl(P, t, 2, ucc[6], uss[6]);
            ry_shfl(P, t, 1, ucc[7], uss[7]);

            applyE(P, cbs4[0], sbs4[0], DC2[18], DS2[18]);
            ciy_smem(P, t, 128, bufA);                 // C0
            {
                float sg = ((t >> 7) & 1) ? gs_sm[0] : -gs_sm[0];
                u64 SE = bc(sg);
                applyG_se(P, bc(gc_sm[0]), SE, SE);
            }
#pragma unroll
            for (int n = 1; n < 10; n++) {
                applyT_tab(P, myCS + (n - 1) * 4);
                if (n == 9)      ciy_lane9(P);
                else if (n == 8) ciy_lane8(P);
                else if (n >= 3) ciy_shfl(P, t, 1 << (7 - n));
                else if (n == 1) ciy_smem(P, t, 64, bufB);
                else             ciy_smem(P, t, 32, bufA);
                u64 C = bc(gc_sm[n]);
                if (n <= 7) {
                    float sg = ((t >> (7 - n)) & 1) ? gs_sm[n] : -gs_sm[n];
                    u64 SE = bc(sg);
                    applyG_se(P, C, SE, SE);
                } else if (n == 8) {
                    u64 SE1 = bc(gs_sm[n]);
                    applyG_se(P, C, f2neg(SE1), SE1);
                } else {
                    applyG_se(P, C, se9p[0], se9p[0]);
                }
            }
            applyF(P, cbs4[2], sbs4[2], DC2[20], DS2[20]);
        }

        // ======== stage 1 (full) ========
        {
            const float* ucc = uc + 10;
            const float* uss = us + 10;
            ry_lane8(P, ucc[8], uss[8]);
            {
                u64 C9 = bc(ucc[9]);
                u64 SW = pk(-uss[9], uss[9]);
                ry_lane9(P, C9, SW);
            }
#pragma unroll
            for (int l = 3; l <= 7; l++)
                ry_shfl(P, t, 1 << (7 - l), ucc[l], uss[l]);
            ry_smem4(P, t, ucc[0], uss[0], ucc[1], uss[1], bufB);
            ry_smem1(P, t, ucc[2], uss[2], bufA);

            applyE(P, cbs4[1], sbs4[1], DC2[19], DS2[19]);
            ciy_smem(P, t, 128, bufB);                 // C0
            {
                float sg = ((t >> 7) & 1) ? gs_sm[10] : -gs_sm[10];
                u64 SE = bc(sg);
                applyG_se(P, bc(gc_sm[10]), SE, SE);
            }
#pragma unroll
            for (int n = 1; n < 10; n++) {
                applyT_tab(P, myCS + (9 + n - 1) * 4);
                if (n == 9)      ciy_lane9(P);
                else if (n == 8) ciy_lane8(P);
                else if (n >= 3) ciy_shfl(P, t, 1 << (7 - n));
                else if (n == 1) ciy_smem(P, t, 64, bufA);
                else             ciy_smem(P, t, 32, bufB);
                int gi = 10 + n;
                u64 C = bc(gc_sm[gi]);
                if (n <= 7) {
                    float sg = ((t >> (7 - n)) & 1) ? gs_sm[gi] : -gs_sm[gi];
                    u64 SE = bc(sg);
                    applyG_se(P, C, SE, SE);
                } else if (n == 8) {
                    u64 SE1 = bc(gs_sm[gi]);
                    applyG_se(P, C, f2neg(SE1), SE1);
                } else {
                    applyG_se(P, C, se9p[1], se9p[1]);
                }
            }
            applyF(P, cbs4[3], sbs4[3], DC2[21], DS2[21]);
        }

        // ---- probs + compress ----
        u64 acc = 0ULL;
#pragma unroll
        for (int j = 0; j < 8; j++) acc = f2fma(P[j], P[j], acc);
        float alo, ahi; upk(acc, alo, ahi);
        float ssq = alo + ahi;
        ssq += __shfl_xor_sync(0xffffffffu, ssq, 1);
        ssq += __shfl_xor_sync(0xffffffffu, ssq, 2);
        if (!(t & 3)) {
            probs_sm[t >> 2] = ssq;
            out[(b * NSTEP + step) * 64 + (t >> 2)] = ssq;
        }
        if ((t >> 2) == tIdx[step + 1]) {
            int pb = (t & 3) * 8;
#pragma unroll
            for (int jj = 0; jj < 8; jj++) phi[pb + jj] = P[jj];
        }
        __syncthreads();
    }

    // ---- second tuple output: measured = inputs[:,1:] as float ----
    if (out_size > 32768 && t < 48) {
        out[32768 + b * 48 + t] = (float)inb[6 + t];
    }
}

} // namespace

extern "C" void kernel_launch(void* const* d_in, const int* in_sizes, int n_in,
                              void* d_out, int out_size) {
    const int*   inputs = nullptr;
    const float* ua     = nullptr;
    const float* nth    = nullptr;
    for (int i = 0; i < n_in; i++) {
        if (in_sizes[i] == 3456)      inputs = (const int*)d_in[i];
        else if (in_sizes[i] == 20)   ua     = (const float*)d_in[i];
        else if (in_sizes[i] == 220)  nth    = (const float*)d_in[i];
    }
    const int dyn_bytes = DYN_U64 * 8;   // 186368
    cudaFuncSetAttribute(rvqe_kernel, cudaFuncAttributeMaxDynamicSharedMemorySize,
                         dyn_bytes);
    rvqe_kernel<<<64, NTH, dyn_bytes>>>(inputs, ua, nth, (float*)d_out, out_size);
}